// round 4
// baseline (speedup 1.0000x reference)
#include <cuda_runtime.h>
#include <cuda_bf16.h>

#define TSEQ   2048
#define BATCH  4096
#define HDIM   32
#define NB     2      // batch rows per warp
#define STAGE  32     // timesteps staged per x-load
#define NSTAGE (TSEQ / STAGE)

typedef unsigned long long ull;

// ---------- packed f32x2 helpers ----------
__device__ __forceinline__ ull pack2(float lo, float hi) {
    ull r;
    asm("mov.b64 %0, {%1, %2};" : "=l"(r) : "f"(lo), "f"(hi));
    return r;
}
__device__ __forceinline__ void unpack2(ull v, float& lo, float& hi) {
    asm("mov.b64 {%0, %1}, %2;" : "=f"(lo), "=f"(hi) : "l"(v));
}
__device__ __forceinline__ ull ffma2(ull a, ull b, ull c) {
    ull d;
    asm("fma.rn.f32x2 %0, %1, %2, %3;" : "=l"(d) : "l"(a), "l"(b), "l"(c));
    return d;
}

// non-hoistable shared load (keeps input weights out of the register file)
__device__ __forceinline__ ull lds64v(unsigned int saddr) {
    ull v;
    asm volatile("ld.shared.b64 %0, [%1];" : "=l"(v) : "r"(saddr));
    return v;
}

// ---------- single-MUFU tanh (sm_75+) ----------
__device__ __forceinline__ float tanhf_fast(float x) {
    float y;
    asm("tanh.approx.f32 %0, %1;" : "=f"(y) : "f"(x));
    return y;
}
// sigmoid(x) = 0.5*tanh(x/2) + 0.5 ; the /2 pre-folded into weights+bias.
__device__ __forceinline__ float sig_from_half(float xh) {
    return fmaf(0.5f, tanhf_fast(xh), 0.5f);
}

// One warp per block, NB=2 batch rows per warp, lane j owns h-index j.
// Gates packed (i,f),(g,o) into f32x2; sigmoid rows pre-scaled by 0.5.
// W_hh register-resident (128 regs); input weights/bias live in smem and are
// re-read every step so total regs fit 14 blocks/SM (single full wave).
__global__ void __launch_bounds__(32, 14)
lstm_warp_kernel(const float* __restrict__ x,
                 const float* __restrict__ W_ih,
                 const float* __restrict__ W_hh,
                 const float* __restrict__ b_ih,
                 const float* __restrict__ b_hh,
                 float* __restrict__ out)
{
    // h duplicated (v,v), double-buffered by step parity
    __shared__ __align__(16) ull hdup[2][NB][HDIM];
    // staged x, duplicated; single buffer (reloaded each stage)
    __shared__ __align__(16) ull xdup[NB][STAGE][4];
    // input-weight rows + bias: [0..2]=wxif, [3..5]=wxgo, [6]=bias_if, [7]=bias_go
    __shared__ __align__(16) ull wxs[8][32];

    const int lane = threadIdx.x & 31;
    const int b0   = blockIdx.x * NB;

    // PyTorch gate rows for this lane: i, f, g, o
    const int r0 = lane;             // i  (sigmoid -> 0.5)
    const int r1 = HDIM + lane;      // f  (sigmoid -> 0.5)
    const int r2 = 2 * HDIM + lane;  // g  (tanh    -> 1.0)
    const int r3 = 3 * HDIM + lane;  // o  (sigmoid -> 0.5)

    // ---- recurrent weights into registers, gate-pair packed ----
    ull wif[HDIM], wgo[HDIM];
#pragma unroll
    for (int k = 0; k < HDIM; k++) {
        wif[k] = pack2(0.5f * W_hh[r0 * HDIM + k], 0.5f * W_hh[r1 * HDIM + k]);
        wgo[k] = pack2(       W_hh[r2 * HDIM + k], 0.5f * W_hh[r3 * HDIM + k]);
    }
    // ---- input weights + combined bias into smem ----
#pragma unroll
    for (int i = 0; i < 3; i++) {
        wxs[i][lane]     = pack2(0.5f * W_ih[r0 * 3 + i], 0.5f * W_ih[r1 * 3 + i]);
        wxs[3 + i][lane] = pack2(       W_ih[r2 * 3 + i], 0.5f * W_ih[r3 * 3 + i]);
    }
    wxs[6][lane] = pack2(0.5f * (b_ih[r0] + b_hh[r0]), 0.5f * (b_ih[r1] + b_hh[r1]));
    wxs[7][lane] = pack2(       (b_ih[r2] + b_hh[r2]), 0.5f * (b_ih[r3] + b_hh[r3]));

    const unsigned int wx_base =
        (unsigned int)__cvta_generic_to_shared(&wxs[0][lane]);

    float c[NB] = {0.0f, 0.0f};
    float h[NB] = {0.0f, 0.0f};
    hdup[0][0][lane] = 0ull;
    hdup[0][1][lane] = 0ull;
    __syncwarp();

#pragma unroll 1
    for (int s = 0; s < NSTAGE; s++) {
        // ---- stage x: NB*STAGE*3 = 192 floats, 6 per lane, coalesced.
        // LDG latency once per 32 steps; hidden by the other resident warps.
#pragma unroll
        for (int it = 0; it < 6; it++) {
            int idx = it * 32 + lane;               // 0..191
            int b   = idx / (STAGE * 3);
            int rem = idx % (STAGE * 3);
            float v = x[(size_t)(b0 + b) * TSEQ * 3 + (size_t)s * STAGE * 3 + rem];
            xdup[b][rem / 3][rem % 3] = pack2(v, v);
        }
        __syncwarp();

#pragma unroll 1
        for (int tt = 0; tt < STAGE; tt++) {
            const int rb = tt & 1;        // read h buffer (global parity: STAGE even)
            const int wb = rb ^ 1;

            // ---- input affine + bias (weights streamed from smem) ----
            ull aif[NB], ago[NB];
            {
                ull w0 = lds64v(wx_base + 0 * 256);
                ull w1 = lds64v(wx_base + 1 * 256);
                ull w2 = lds64v(wx_base + 2 * 256);
                ull g0 = lds64v(wx_base + 3 * 256);
                ull g1 = lds64v(wx_base + 4 * 256);
                ull g2 = lds64v(wx_base + 5 * 256);
                ull bi = lds64v(wx_base + 6 * 256);
                ull bg = lds64v(wx_base + 7 * 256);
#pragma unroll
                for (int b = 0; b < NB; b++) {
                    ulonglong2 x01 = *reinterpret_cast<const ulonglong2*>(&xdup[b][tt][0]);
                    ull x2 = xdup[b][tt][2];
                    aif[b] = ffma2(x01.x, w0, ffma2(x01.y, w1, ffma2(x2, w2, bi)));
                    ago[b] = ffma2(x01.x, g0, ffma2(x01.y, g1, ffma2(x2, g2, bg)));
                }
            }

            // ---- recurrent matvec, 4 independent lat-covering chains ----
#pragma unroll
            for (int kk = 0; kk < HDIM; kk += 2) {
                ulonglong2 hd0 = *reinterpret_cast<const ulonglong2*>(&hdup[rb][0][kk]);
                ulonglong2 hd1 = *reinterpret_cast<const ulonglong2*>(&hdup[rb][1][kk]);
                aif[0] = ffma2(wif[kk],     hd0.x, aif[0]);
                ago[0] = ffma2(wgo[kk],     hd0.x, ago[0]);
                aif[1] = ffma2(wif[kk],     hd1.x, aif[1]);
                ago[1] = ffma2(wgo[kk],     hd1.x, ago[1]);
                aif[0] = ffma2(wif[kk + 1], hd0.y, aif[0]);
                ago[0] = ffma2(wgo[kk + 1], hd0.y, ago[0]);
                aif[1] = ffma2(wif[kk + 1], hd1.y, aif[1]);
                ago[1] = ffma2(wgo[kk + 1], hd1.y, ago[1]);
            }

            // ---- activations + state update (i,f,o preacts already halved) ----
#pragma unroll
            for (int b = 0; b < NB; b++) {
                float ih, fh, gp, oh;
                unpack2(aif[b], ih, fh);
                unpack2(ago[b], gp, oh);
                float ig = sig_from_half(ih);
                float fg = sig_from_half(fh);
                float gg = tanhf_fast(gp);
                float og = sig_from_half(oh);
                c[b] = fmaf(fg, c[b], ig * gg);
                h[b] = og * tanhf_fast(c[b]);
                hdup[wb][b][lane] = pack2(h[b], h[b]);
            }
            __syncwarp();   // h writes visible before next step's reads
        }
        __syncwarp();       // all steps of this stage done before x overwrite
    }

#pragma unroll
    for (int b = 0; b < NB; b++)
        out[(size_t)(b0 + b) * HDIM + lane] = h[b];
}

extern "C" void kernel_launch(void* const* d_in, const int* in_sizes, int n_in,
                              void* d_out, int out_size)
{
    const float* x    = (const float*)d_in[0];
    const float* W_ih = (const float*)d_in[1];
    const float* W_hh = (const float*)d_in[2];
    const float* b_ih = (const float*)d_in[3];
    const float* b_hh = (const float*)d_in[4];
    float* out = (float*)d_out;

    lstm_warp_kernel<<<BATCH / NB, 32>>>(x, W_ih, W_hh, b_ih, b_hh, out);
}

// round 5
// speedup vs baseline: 1.4706x; 1.4706x over previous
#include <cuda_runtime.h>
#include <cuda_bf16.h>

#define TSEQ   2048
#define BATCH  4096
#define HDIM   32
#define STAGE  16
#define NSTAGE (TSEQ / STAGE)
#define NBMAX  7
#define NFULL  146          // blocks with 28 rows (4 warps x NB=7)

typedef unsigned long long ull;

// ---------- packed f32x2 helpers ----------
__device__ __forceinline__ ull pack2(float lo, float hi) {
    ull r;
    asm("mov.b64 %0, {%1, %2};" : "=l"(r) : "f"(lo), "f"(hi));
    return r;
}
__device__ __forceinline__ void unpack2(ull v, float& lo, float& hi) {
    asm("mov.b64 {%0, %1}, %2;" : "=f"(lo), "=f"(hi) : "l"(v));
}
__device__ __forceinline__ ull ffma2(ull a, ull b, ull c) {
    ull d;
    asm("fma.rn.f32x2 %0, %1, %2, %3;" : "=l"(d) : "l"(a), "l"(b), "l"(c));
    return d;
}
__device__ __forceinline__ ull add2(ull a, ull b) {
    ull d;
    asm("add.rn.f32x2 %0, %1, %2;" : "=l"(d) : "l"(a), "l"(b));
    return d;
}

// ---------- single-MUFU tanh (sm_75+) ----------
__device__ __forceinline__ float tanhf_fast(float x) {
    float y;
    asm("tanh.approx.f32 %0, %1;" : "=f"(y) : "f"(x));
    return y;
}
// sigmoid(x) = 0.5*tanh(x/2) + 0.5 ; the /2 pre-folded into weights+bias.
__device__ __forceinline__ float sig_from_half(float xh) {
    return fmaf(0.5f, tanhf_fast(xh), 0.5f);
}

// One warp processes NB batch rows serially through all 2048 steps.
// Lane j owns h-index j. Gates packed (i,f),(g,o) into f32x2; sigmoid rows
// pre-scaled by 0.5. W_hh fully register-resident (128 regs/lane).
template <int NB>
__device__ __forceinline__ void lstm_run(
    const float* __restrict__ x,
    const float* __restrict__ W_ih,
    const float* __restrict__ W_hh,
    const float* __restrict__ b_ih,
    const float* __restrict__ b_hh,
    float* __restrict__ out,
    ull (*hdup)[NBMAX][HDIM],        // [2][NBMAX][32] this warp's slice
    ull (*xdup)[STAGE][4],           // [NBMAX][STAGE][4]
    int row0, int lane)
{
    constexpr int NX = (NB * STAGE * 3 + 31) / 32;   // prefetch regs per lane

    // PyTorch gate rows for this lane: i, f, g, o
    const int r0 = lane;             // i  (sigmoid -> 0.5)
    const int r1 = HDIM + lane;      // f  (sigmoid -> 0.5)
    const int r2 = 2 * HDIM + lane;  // g  (tanh    -> 1.0)
    const int r3 = 3 * HDIM + lane;  // o  (sigmoid -> 0.5)

    // ---- recurrent weights into registers, gate-pair packed ----
    ull wif[HDIM], wgo[HDIM];
#pragma unroll
    for (int k = 0; k < HDIM; k++) {
        wif[k] = pack2(0.5f * W_hh[r0 * HDIM + k], 0.5f * W_hh[r1 * HDIM + k]);
        wgo[k] = pack2(       W_hh[r2 * HDIM + k], 0.5f * W_hh[r3 * HDIM + k]);
    }
    // ---- input weights + combined bias (registers; budget is ample) ----
    ull wxif[3], wxgo[3];
#pragma unroll
    for (int i = 0; i < 3; i++) {
        wxif[i] = pack2(0.5f * W_ih[r0 * 3 + i], 0.5f * W_ih[r1 * 3 + i]);
        wxgo[i] = pack2(       W_ih[r2 * 3 + i], 0.5f * W_ih[r3 * 3 + i]);
    }
    const ull bias_if = pack2(0.5f * (b_ih[r0] + b_hh[r0]),
                              0.5f * (b_ih[r1] + b_hh[r1]));
    const ull bias_go = pack2(       (b_ih[r2] + b_hh[r2]),
                              0.5f * (b_ih[r3] + b_hh[r3]));

    float c[NB];
#pragma unroll
    for (int b = 0; b < NB; b++) {
        c[b] = 0.0f;
        hdup[0][b][lane] = 0ull;
    }

    // ---- stage 0 of x ----
#pragma unroll
    for (int it = 0; it < NX; it++) {
        int idx = it * 32 + lane;
        if (idx < NB * STAGE * 3) {
            int b   = idx / (STAGE * 3);
            int rem = idx % (STAGE * 3);
            float v = x[(size_t)(row0 + b) * TSEQ * 3 + rem];
            xdup[b][rem / 3][rem % 3] = pack2(v, v);
        }
    }
    __syncwarp();

#pragma unroll 1
    for (int s = 0; s < NSTAGE; s++) {
        // ---- prefetch next stage's x into registers (hidden over 16 steps) ----
        float xr[NX];
        if (s + 1 < NSTAGE) {
#pragma unroll
            for (int it = 0; it < NX; it++) {
                int idx = it * 32 + lane;
                if (idx < NB * STAGE * 3) {
                    int b   = idx / (STAGE * 3);
                    int rem = idx % (STAGE * 3);
                    xr[it] = x[(size_t)(row0 + b) * TSEQ * 3
                               + (size_t)(s + 1) * STAGE * 3 + rem];
                }
            }
        }

#pragma unroll 1
        for (int tt = 0; tt < STAGE; tt++) {
            const int rb = tt & 1;          // STAGE even -> parity consistent
            const int wb = rb ^ 1;

            // Per-row pipeline: act(b) overlaps matvec(b+1) in the scheduler.
#pragma unroll
            for (int b = 0; b < NB; b++) {
                // ---- input affine + bias (seed chain A) ----
                ulonglong2 x01 = *reinterpret_cast<const ulonglong2*>(&xdup[b][tt][0]);
                ull x2 = xdup[b][tt][2];
                ull aifA = ffma2(x01.x, wxif[0], ffma2(x01.y, wxif[1], ffma2(x2, wxif[2], bias_if)));
                ull agoA = ffma2(x01.x, wxgo[0], ffma2(x01.y, wxgo[1], ffma2(x2, wxgo[2], bias_go)));
                ull aifB = 0ull, agoB = 0ull;

                // ---- recurrent matvec: 4 chains (A/B x if/go), rt-2 slack ----
#pragma unroll
                for (int kk = 0; kk < HDIM; kk += 4) {
                    ulonglong2 hd0 = *reinterpret_cast<const ulonglong2*>(&hdup[rb][b][kk]);
                    ulonglong2 hd1 = *reinterpret_cast<const ulonglong2*>(&hdup[rb][b][kk + 2]);
                    aifA = ffma2(wif[kk],     hd0.x, aifA);
                    agoA = ffma2(wgo[kk],     hd0.x, agoA);
                    aifB = ffma2(wif[kk + 1], hd0.y, aifB);
                    agoB = ffma2(wgo[kk + 1], hd0.y, agoB);
                    aifA = ffma2(wif[kk + 2], hd1.x, aifA);
                    agoA = ffma2(wgo[kk + 2], hd1.x, agoA);
                    aifB = ffma2(wif[kk + 3], hd1.y, aifB);
                    agoB = ffma2(wgo[kk + 3], hd1.y, agoB);
                }
                ull tif = add2(aifA, aifB);
                ull tgo = add2(agoA, agoB);

                // ---- activations + state update (i,f,o preacts pre-halved) ----
                float ih, fh, gp, oh;
                unpack2(tif, ih, fh);
                unpack2(tgo, gp, oh);
                float ig = sig_from_half(ih);
                float fg = sig_from_half(fh);
                float gg = tanhf_fast(gp);
                float og = sig_from_half(oh);
                c[b] = fmaf(fg, c[b], ig * gg);
                float hb = og * tanhf_fast(c[b]);
                hdup[wb][b][lane] = pack2(hb, hb);
            }
            __syncwarp();   // all lanes' h published before next step's reads
        }

        // ---- commit prefetched x (reads of this stage are behind the last sync) ----
        if (s + 1 < NSTAGE) {
#pragma unroll
            for (int it = 0; it < NX; it++) {
                int idx = it * 32 + lane;
                if (idx < NB * STAGE * 3) {
                    int b   = idx / (STAGE * 3);
                    int rem = idx % (STAGE * 3);
                    xdup[b][rem / 3][rem % 3] = pack2(xr[it], xr[it]);
                }
            }
            __syncwarp();
        }
    }

    // Last step wrote parity buffer 0 (tt=15 -> wb=0).
#pragma unroll
    for (int b = 0; b < NB; b++) {
        float lo, hi;
        unpack2(hdup[0][b][lane], lo, hi);
        out[(size_t)(row0 + b) * HDIM + lane] = lo;
    }
}

// 147 blocks x 4 warps: blocks 0..145 -> 28 rows (NB=7/warp), block 146 -> 8 rows.
// One block per SM, one warp per SMSP: uniform load, zero wave tail.
__global__ void __launch_bounds__(128, 1)
lstm_kernel(const float* __restrict__ x,
            const float* __restrict__ W_ih,
            const float* __restrict__ W_hh,
            const float* __restrict__ b_ih,
            const float* __restrict__ b_hh,
            float* __restrict__ out)
{
    __shared__ __align__(16) ull hd[4][2][NBMAX][HDIM];
    __shared__ __align__(16) ull xd[4][NBMAX][STAGE][4];

    const int wid  = threadIdx.x >> 5;
    const int lane = threadIdx.x & 31;
    const int bid  = blockIdx.x;

    if (bid < NFULL) {
        lstm_run<7>(x, W_ih, W_hh, b_ih, b_hh, out,
                    hd[wid], xd[wid], bid * 28 + wid * 7, lane);
    } else {
        lstm_run<2>(x, W_ih, W_hh, b_ih, b_hh, out,
                    hd[wid], xd[wid], NFULL * 28 + wid * 2, lane);
    }
}

extern "C" void kernel_launch(void* const* d_in, const int* in_sizes, int n_in,
                              void* d_out, int out_size)
{
    const float* x    = (const float*)d_in[0];
    const float* W_ih = (const float*)d_in[1];
    const float* W_hh = (const float*)d_in[2];
    const float* b_ih = (const float*)d_in[3];
    const float* b_hh = (const float*)d_in[4];
    float* out = (float*)d_out;

    lstm_kernel<<<147, 128>>>(x, W_ih, W_hh, b_ih, b_hh, out);
}

// round 6
// speedup vs baseline: 1.9958x; 1.3572x over previous
#include <cuda_runtime.h>
#include <cuda_bf16.h>

#define TSEQ   2048
#define BATCH  4096
#define HDIM   32
#define STAGE  16
#define NSTAGE (TSEQ / STAGE)
#define NBMAX  4
#define NB28BLOCKS 100   // blocks carrying 28 rows; remaining 48 carry 27

typedef unsigned long long ull;

// ---------- packed f32x2 helpers ----------
__device__ __forceinline__ ull pack2(float lo, float hi) {
    ull r;
    asm("mov.b64 %0, {%1, %2};" : "=l"(r) : "f"(lo), "f"(hi));
    return r;
}
__device__ __forceinline__ void unpack2(ull v, float& lo, float& hi) {
    asm("mov.b64 {%0, %1}, %2;" : "=f"(lo), "=f"(hi) : "l"(v));
}
__device__ __forceinline__ ull ffma2(ull a, ull b, ull c) {
    ull d;
    asm("fma.rn.f32x2 %0, %1, %2, %3;" : "=l"(d) : "l"(a), "l"(b), "l"(c));
    return d;
}

// ---------- single-MUFU tanh (sm_75+) ----------
__device__ __forceinline__ float tanhf_fast(float x) {
    float y;
    asm("tanh.approx.f32 %0, %1;" : "=f"(y) : "f"(x));
    return y;
}
// sigmoid(x) = 0.5*tanh(x/2) + 0.5 ; the /2 pre-folded into weights+bias.
__device__ __forceinline__ float sig_from_half(float xh) {
    return fmaf(0.5f, tanhf_fast(xh), 0.5f);
}

// One warp processes NB batch rows through all 2048 steps.
// Lane j owns h-index j. Gates packed (i,f),(g,o) into f32x2; sigmoid rows
// pre-scaled by 0.5. W_hh fully register-resident (128 regs/lane).
template <int NB>
__device__ __forceinline__ void lstm_run(
    const float* __restrict__ x,
    const float* __restrict__ W_ih,
    const float* __restrict__ W_hh,
    const float* __restrict__ b_ih,
    const float* __restrict__ b_hh,
    float* __restrict__ out,
    ull (*hdup)[NBMAX][HDIM],        // [2][NBMAX][32] this warp's slice
    ull (*xdup)[STAGE][4],           // [NBMAX][STAGE][4]
    int row0, int lane)
{
    constexpr int NX = (NB * STAGE * 3 + 31) / 32;

    // PyTorch gate rows for this lane: i, f, g, o
    const int r0 = lane;             // i  (sigmoid -> 0.5)
    const int r1 = HDIM + lane;      // f  (sigmoid -> 0.5)
    const int r2 = 2 * HDIM + lane;  // g  (tanh    -> 1.0)
    const int r3 = 3 * HDIM + lane;  // o  (sigmoid -> 0.5)

    // ---- recurrent weights into registers, gate-pair packed ----
    ull wif[HDIM], wgo[HDIM];
#pragma unroll
    for (int k = 0; k < HDIM; k++) {
        wif[k] = pack2(0.5f * W_hh[r0 * HDIM + k], 0.5f * W_hh[r1 * HDIM + k]);
        wgo[k] = pack2(       W_hh[r2 * HDIM + k], 0.5f * W_hh[r3 * HDIM + k]);
    }
    // ---- input weights + combined bias ----
    ull wxif[3], wxgo[3];
#pragma unroll
    for (int i = 0; i < 3; i++) {
        wxif[i] = pack2(0.5f * W_ih[r0 * 3 + i], 0.5f * W_ih[r1 * 3 + i]);
        wxgo[i] = pack2(       W_ih[r2 * 3 + i], 0.5f * W_ih[r3 * 3 + i]);
    }
    const ull bias_if = pack2(0.5f * (b_ih[r0] + b_hh[r0]),
                              0.5f * (b_ih[r1] + b_hh[r1]));
    const ull bias_go = pack2(       (b_ih[r2] + b_hh[r2]),
                              0.5f * (b_ih[r3] + b_hh[r3]));

    float c[NB];
#pragma unroll
    for (int b = 0; b < NB; b++) {
        c[b] = 0.0f;
        hdup[0][b][lane] = 0ull;
    }

    // ---- stage 0 of x ----
#pragma unroll
    for (int it = 0; it < NX; it++) {
        int idx = it * 32 + lane;
        if (idx < NB * STAGE * 3) {
            int b   = idx / (STAGE * 3);
            int rem = idx % (STAGE * 3);
            float v = x[(size_t)(row0 + b) * TSEQ * 3 + rem];
            xdup[b][rem / 3][rem % 3] = pack2(v, v);
        }
    }
    __syncwarp();

#pragma unroll 1
    for (int s = 0; s < NSTAGE; s++) {
        // ---- prefetch next stage's x into registers (hidden over 16 steps) ----
        float xr[NX];
        if (s + 1 < NSTAGE) {
#pragma unroll
            for (int it = 0; it < NX; it++) {
                int idx = it * 32 + lane;
                if (idx < NB * STAGE * 3) {
                    int b   = idx / (STAGE * 3);
                    int rem = idx % (STAGE * 3);
                    xr[it] = x[(size_t)(row0 + b) * TSEQ * 3
                               + (size_t)(s + 1) * STAGE * 3 + rem];
                }
            }
        }

#pragma unroll 1
        for (int tt = 0; tt < STAGE; tt++) {
            const int rb = tt & 1;
            const int wb = rb ^ 1;

            // ---- input affine + bias (early LDS, independent per row) ----
            ull aif[NB], ago[NB];
#pragma unroll
            for (int b = 0; b < NB; b++) {
                ulonglong2 x01 = *reinterpret_cast<const ulonglong2*>(&xdup[b][tt][0]);
                ull x2 = xdup[b][tt][2];
                aif[b] = ffma2(x01.x, wxif[0], ffma2(x01.y, wxif[1], ffma2(x2, wxif[2], bias_if)));
                ago[b] = ffma2(x01.x, wxgo[0], ffma2(x01.y, wxgo[1], ffma2(x2, wxgo[2], bias_go)));
            }

            // ---- recurrent matvec: rows interleaved in kk so 2*NB chains
            // stay independent and LDS hoists ahead of use ----
#pragma unroll
            for (int kk = 0; kk < HDIM; kk += 2) {
#pragma unroll
                for (int b = 0; b < NB; b++) {
                    ulonglong2 hd = *reinterpret_cast<const ulonglong2*>(&hdup[rb][b][kk]);
                    aif[b] = ffma2(wif[kk],     hd.x, aif[b]);
                    ago[b] = ffma2(wgo[kk],     hd.x, ago[b]);
                    aif[b] = ffma2(wif[kk + 1], hd.y, aif[b]);
                    ago[b] = ffma2(wgo[kk + 1], hd.y, ago[b]);
                }
            }

            // ---- activations + state update (i,f,o preacts pre-halved) ----
#pragma unroll
            for (int b = 0; b < NB; b++) {
                float ih, fh, gp, oh;
                unpack2(aif[b], ih, fh);
                unpack2(ago[b], gp, oh);
                float ig = sig_from_half(ih);
                float fg = sig_from_half(fh);
                float gg = tanhf_fast(gp);
                float og = sig_from_half(oh);
                c[b] = fmaf(fg, c[b], ig * gg);
                float hb = og * tanhf_fast(c[b]);
                hdup[wb][b][lane] = pack2(hb, hb);
            }
            __syncwarp();   // h published before next step's reads
        }

        // ---- commit prefetched x ----
        if (s + 1 < NSTAGE) {
#pragma unroll
            for (int it = 0; it < NX; it++) {
                int idx = it * 32 + lane;
                if (idx < NB * STAGE * 3) {
                    int b   = idx / (STAGE * 3);
                    int rem = idx % (STAGE * 3);
                    xdup[b][rem / 3][rem % 3] = pack2(xr[it], xr[it]);
                }
            }
            __syncwarp();
        }
    }

    // Last step (tt=15) wrote parity buffer 0.
#pragma unroll
    for (int b = 0; b < NB; b++) {
        float lo, hi;
        unpack2(hdup[0][b][lane], lo, hi);
        out[(size_t)(row0 + b) * HDIM + lane] = lo;
    }
}

// Row distribution within a block. wid%4 -> SMSP, so wid i pairs with wid i+4.
// 28-row blocks: NB = 4,4,4,4,3,3,3,3  -> every SMSP pair carries 4+3 = 7 rows.
// 27-row blocks: NB = 4,4,4,3,3,3,3,3  -> pairs 7,7,7,6.
__device__ __constant__ int NB28[8]  = {4, 4, 4, 4, 3, 3, 3, 3};
__device__ __constant__ int OFF28[8] = {0, 4, 8, 12, 16, 19, 22, 25};
__device__ __constant__ int NB27[8]  = {4, 4, 4, 3, 3, 3, 3, 3};
__device__ __constant__ int OFF27[8] = {0, 4, 8, 12, 15, 18, 21, 24};

// 148 blocks x 256 threads: exactly one block per SM, 2 warps per SMSP with
// controlled pairing; single wave, zero tail.
__global__ void __launch_bounds__(256, 1)
lstm_kernel(const float* __restrict__ x,
            const float* __restrict__ W_ih,
            const float* __restrict__ W_hh,
            const float* __restrict__ b_ih,
            const float* __restrict__ b_hh,
            float* __restrict__ out)
{
    __shared__ __align__(16) ull hd[8][2][NBMAX][HDIM];
    __shared__ __align__(16) ull xd[8][NBMAX][STAGE][4];

    const int wid  = threadIdx.x >> 5;
    const int lane = threadIdx.x & 31;
    const int bid  = blockIdx.x;

    int row0, nb;
    if (bid < NB28BLOCKS) {
        row0 = bid * 28 + OFF28[wid];
        nb   = NB28[wid];
    } else {
        row0 = NB28BLOCKS * 28 + (bid - NB28BLOCKS) * 27 + OFF27[wid];
        nb   = NB27[wid];
    }

    if (nb == 4) {
        lstm_run<4>(x, W_ih, W_hh, b_ih, b_hh, out, hd[wid], xd[wid], row0, lane);
    } else {
        lstm_run<3>(x, W_ih, W_hh, b_ih, b_hh, out, hd[wid], xd[wid], row0, lane);
    }
}

extern "C" void kernel_launch(void* const* d_in, const int* in_sizes, int n_in,
                              void* d_out, int out_size)
{
    const float* x    = (const float*)d_in[0];
    const float* W_ih = (const float*)d_in[1];
    const float* W_hh = (const float*)d_in[2];
    const float* b_ih = (const float*)d_in[3];
    const float* b_hh = (const float*)d_in[4];
    float* out = (float*)d_out;

    lstm_kernel<<<148, 256>>>(x, W_ih, W_hh, b_ih, b_hh, out);
}